// round 6
// baseline (speedup 1.0000x reference)
#include <cuda_runtime.h>

// ============================================================================
// ChebConvNet (K=1 ChebConv == dense layer; edge_index is dead):
//   h = silu(x@W0+b0); h = silu(h@W1+b1); h = silu(h@W2+b2);
//   out = log_softmax(h@W3+b3)
// Fully fused single kernel. Row tiles of 32 in static SMEM ping-pong buffers.
// Weights stream via __ldg (L1/L2 resident: 216 KB total, same line per warp).
// fp32 math with packed fma.rn.f32x2 (FFMA2) for 2x fp32 FMA rate on sm_103a.
// ============================================================================

#define TR 32          // rows per block tile
#define DF 128         // feature dim
#define NC 40          // classes

#define FMA2(acc, a, b) \
    asm("fma.rn.f32x2 %0, %1, %2, %0;" : "+l"(acc) : "l"(a), "l"(b))

__device__ __forceinline__ unsigned long long pack2(float lo, float hi) {
    unsigned long long r;
    asm("mov.b64 %0, {%1, %2};" : "=l"(r) : "f"(lo), "f"(hi));
    return r;
}
__device__ __forceinline__ void unpack2(unsigned long long v, float& lo, float& hi) {
    asm("mov.b64 {%0, %1}, %2;" : "=f"(lo), "=f"(hi) : "l"(v));
}
__device__ __forceinline__ float silu_f(float v) {
    // v * sigmoid(v) = v / (1 + exp(-v)); __expf/__fdividef err ~2^-21 << 1e-3
    return __fdividef(v, 1.0f + __expf(-v));
}

// One 128->128 dense layer + SiLU for a TR x 128 tile.
// Mapping: warp w owns rows [4w, 4w+4); lane owns cols [4*lane, 4*lane+4).
// Per k: 1 LDG.128 (W row, L1-hit / broadcast across warps), 4 LDS broadcasts
// (h values), 8 FFMA2 -> fma-pipe-bound near FFMA2 peak.
__device__ __forceinline__ void dense128_silu(
    const float* hin, float* hout,
    const float* __restrict__ W, const float* __restrict__ b,
    int lane, int warp)
{
    const int j0 = lane * 4;
    const int r0 = warp * 4;

    unsigned long long acc[4][2];
    const float4 bb = __ldg((const float4*)(b + j0));
    const unsigned long long bi0 = pack2(bb.x, bb.y);
    const unsigned long long bi1 = pack2(bb.z, bb.w);
#pragma unroll
    for (int r = 0; r < 4; r++) { acc[r][0] = bi0; acc[r][1] = bi1; }

#pragma unroll 8
    for (int k = 0; k < DF; k++) {
        const float4 w4 = __ldg((const float4*)(W + k * DF + j0));
        const unsigned long long w01 = pack2(w4.x, w4.y);
        const unsigned long long w23 = pack2(w4.z, w4.w);
#pragma unroll
        for (int r = 0; r < 4; r++) {
            const float hv = hin[(r0 + r) * DF + k];   // warp-broadcast LDS
            const unsigned long long h2 = pack2(hv, hv);
            FMA2(acc[r][0], h2, w01);
            FMA2(acc[r][1], h2, w23);
        }
    }

#pragma unroll
    for (int r = 0; r < 4; r++) {
        float a, b2, c2, d2;
        unpack2(acc[r][0], a, b2);
        unpack2(acc[r][1], c2, d2);
        float4 o;
        o.x = silu_f(a); o.y = silu_f(b2); o.z = silu_f(c2); o.w = silu_f(d2);
        *(float4*)(hout + (r0 + r) * DF + j0) = o;
    }
}

__global__ __launch_bounds__(256)
void chebnet_fused_kernel(
    const float* __restrict__ x,
    const float* __restrict__ W0, const float* __restrict__ b0,
    const float* __restrict__ W1, const float* __restrict__ b1,
    const float* __restrict__ W2, const float* __restrict__ b2,
    const float* __restrict__ W3, const float* __restrict__ b3,
    float* __restrict__ out)
{
    __shared__ float bufA[TR * DF];       // 16 KB
    __shared__ float bufB[TR * DF];       // 16 KB
    __shared__ float logits[TR * NC];     // 5 KB
    __shared__ float rmax[TR];
    __shared__ float rlse[TR];

    const int tid  = threadIdx.x;
    const int lane = tid & 31;
    const int warp = tid >> 5;
    const long long row0 = (long long)blockIdx.x * TR;

    // ---- load x tile (coalesced float4) ----
    {
        const float4* gx = (const float4*)(x + row0 * DF);
        float4* sA = (float4*)bufA;
#pragma unroll
        for (int i = 0; i < (TR * DF / 4) / 256; i++)    // 4 iters
            sA[tid + i * 256] = gx[tid + i * 256];
    }
    __syncthreads();

    // ---- hidden layers (ping-pong) ----
    dense128_silu(bufA, bufB, W0, b0, lane, warp);
    __syncthreads();
    dense128_silu(bufB, bufA, W1, b1, lane, warp);
    __syncthreads();
    dense128_silu(bufA, bufB, W2, b2, lane, warp);
    __syncthreads();

    // ---- output layer: 128 -> 40 (lanes 0..19 handle 2 cols each) ----
    if (lane < 20) {
        const int j0 = lane * 2;
        const int r0 = warp * 4;
        unsigned long long acc[4];
        const float2 bb = *(const float2*)(b3 + j0);
        const unsigned long long bi = pack2(bb.x, bb.y);
#pragma unroll
        for (int r = 0; r < 4; r++) acc[r] = bi;

#pragma unroll 8
        for (int k = 0; k < DF; k++) {
            const float2 w2 = __ldg((const float2*)(W3 + k * NC + j0));
            const unsigned long long wp = pack2(w2.x, w2.y);
#pragma unroll
            for (int r = 0; r < 4; r++) {
                const float hv = bufB[(r0 + r) * DF + k];
                const unsigned long long h2 = pack2(hv, hv);
                FMA2(acc[r], h2, wp);
            }
        }
#pragma unroll
        for (int r = 0; r < 4; r++) {
            float lo, hi;
            unpack2(acc[r], lo, hi);
            logits[(r0 + r) * NC + j0]     = lo;
            logits[(r0 + r) * NC + j0 + 1] = hi;
        }
    }
    __syncthreads();

    // ---- log-softmax stats: one thread per row ----
    if (tid < TR) {
        const float* lrow = &logits[tid * NC];
        float m = lrow[0];
#pragma unroll
        for (int c = 1; c < NC; c++) m = fmaxf(m, lrow[c]);
        float s = 0.0f;
#pragma unroll
        for (int c = 0; c < NC; c++) s += __expf(lrow[c] - m);
        rmax[tid] = m;
        rlse[tid] = __logf(s);
    }
    __syncthreads();

    // ---- coalesced output write ----
    {
        float* gout = out + row0 * NC;
        for (int i = tid; i < TR * NC; i += 256) {
            const int r = i / NC;
            gout[i] = logits[i] - rmax[r] - rlse[r];
        }
    }
}

// ============================================================================
// kernel_launch: single fused launch, graph-capturable, no allocations.
// Input order (metadata): x, edge_index (unused), W0,b0, W1,b1, W2,b2, W3,b3
// ============================================================================
extern "C" void kernel_launch(void* const* d_in, const int* in_sizes, int n_in,
                              void* d_out, int out_size)
{
    (void)in_sizes; (void)n_in; (void)out_size;
    const float* x  = (const float*)d_in[0];
    // d_in[1] = edge_index (int64), dead in K=1 ChebConv — intentionally unused
    const float* W0 = (const float*)d_in[2];
    const float* b0 = (const float*)d_in[3];
    const float* W1 = (const float*)d_in[4];
    const float* b1 = (const float*)d_in[5];
    const float* W2 = (const float*)d_in[6];
    const float* b2 = (const float*)d_in[7];
    const float* W3 = (const float*)d_in[8];
    const float* b3 = (const float*)d_in[9];
    float* out = (float*)d_out;

    const int n_nodes = 200000;
    const int grid = n_nodes / TR;   // 6250, exact
    chebnet_fused_kernel<<<grid, 256>>>(x, W0, b0, W1, b1, W2, b2, W3, b3, out);
}

// round 9
// speedup vs baseline: 1.6409x; 1.6409x over previous
#include <cuda_runtime.h>
#include <cuda_bf16.h>
#include <cstdint>

// ============================================================================
// ChebConvNet fused MLP via mma.sync (HMMA, baseline PTX — no sm_103a features).
//   h=silu(x@W0+b0); h=silu(h@W1+b1); h=silu(h@W2+b2); out=log_softmax(h@W3+b3)
// Key identity: m16n8k16 C-frag layout == A-frag layout, so each warp's 16-row
// output IS the next layer's A operand. Layers chain inside the warp.
// bf16 hi/lo 3-term split (AhiBhi + AhiBlo + AloBhi), fp32 accumulate.
// ============================================================================

#define N_NODES 200000
#define DF      128
#define NC      40
#define THREADS 256
#define NBLOCKS ((N_NODES + 127) / 128)   // 1563

#define SP 136                              // padded row stride (bf16 elems)
#define LAYER_U4 (2 * 128 * SP * 2 / 16)    // 4352 uint4 per layer (hi+lo)
#define HALF_BYTES (128 * SP * 2)           // 34816: lo offset inside B buffer
#define SCR_OFF    (128 * SP * 2 * 2)       // 69632: scratch after B buffer
#define WARP_SCR   (16 * SP * 2 * 2)        // 8704 bytes per warp (hi+lo)
#define SCR_HALF   (16 * SP * 2)            // 4352: lo offset inside warp scratch
#define SMEM_TOTAL (SCR_OFF + 8 * WARP_SCR) // 139264

// Prepped weights: per layer, [n:128][k:SP] bf16 hi then lo (padded image,
// copied verbatim into smem). Layer 3 rows 40..127 are zero.
__device__ uint4 g_Wp4[4 * LAYER_U4];

__device__ __forceinline__ uint32_t s2u(const void* p) {
    uint32_t a;
    asm("{ .reg .u64 t; cvta.to.shared.u64 t, %1; cvt.u32.u64 %0, t; }" : "=r"(a) : "l"(p));
    return a;
}

#define LDSM4(r0, r1, r2, r3, a) \
    asm volatile("ldmatrix.sync.aligned.m8n8.x4.shared.b16 {%0,%1,%2,%3}, [%4];" \
                 : "=r"(r0), "=r"(r1), "=r"(r2), "=r"(r3) : "r"(a))
#define LDSM2(r0, r1, a) \
    asm volatile("ldmatrix.sync.aligned.m8n8.x2.shared.b16 {%0,%1}, [%2];" \
                 : "=r"(r0), "=r"(r1) : "r"(a))
#define MMA(c0, c1, c2, c3, a0, a1, a2, a3, b0, b1) \
    asm volatile("mma.sync.aligned.m16n8k16.row.col.f32.bf16.bf16.f32 " \
                 "{%0,%1,%2,%3}, {%4,%5,%6,%7}, {%8,%9}, {%0,%1,%2,%3};" \
                 : "+f"(c0), "+f"(c1), "+f"(c2), "+f"(c3) \
                 : "r"(a0), "r"(a1), "r"(a2), "r"(a3), "r"(b0), "r"(b1))

__device__ __forceinline__ uint32_t pkb(__nv_bfloat16 a, __nv_bfloat16 b) {
    return (uint32_t)__bfloat16_as_ushort(a) | ((uint32_t)__bfloat16_as_ushort(b) << 16);
}
// split (a,b) into packed bf16 hi + packed bf16 residual
__device__ __forceinline__ void split2(float a, float b, uint32_t& hi, uint32_t& lo) {
    __nv_bfloat16 ha = __float2bfloat16_rn(a), hb = __float2bfloat16_rn(b);
    hi = pkb(ha, hb);
    lo = pkb(__float2bfloat16_rn(a - __bfloat162float(ha)),
             __float2bfloat16_rn(b - __bfloat162float(hb)));
}
__device__ __forceinline__ float silu_f(float v) {
    return __fdividef(v, 1.0f + __expf(-v));
}

// ============================================================================
// Prep: W[k][n] -> padded [n][SP] bf16 hi/lo images (layer 3 zero-padded to 128)
// ============================================================================
__global__ __launch_bounds__(256)
void prep_weights(const float* __restrict__ W0, const float* __restrict__ W1,
                  const float* __restrict__ W2, const float* __restrict__ W3) {
    int e = blockIdx.x * 256 + threadIdx.x;        // over 4*128*128
    if (e >= 4 * 128 * 128) return;
    int l = e >> 14, r = e & 16383, n = r >> 7, k = r & 127;
    float v;
    if (l < 3) {
        const float* W = (l == 0) ? W0 : ((l == 1) ? W1 : W2);
        v = W[k * 128 + n];
    } else {
        v = (n < NC) ? W3[k * NC + n] : 0.0f;
    }
    __nv_bfloat16* gw = (__nv_bfloat16*)g_Wp4;
    size_t base = (size_t)l * (2 * 128 * SP);
    __nv_bfloat16 h = __float2bfloat16_rn(v);
    gw[base + n * SP + k] = h;
    gw[base + 128 * SP + n * SP + k] = __float2bfloat16_rn(v - __bfloat162float(h));
}

// ============================================================================
// Main kernel: 8 warps x 16 rows; all activations warp-resident.
// ============================================================================
__global__ __launch_bounds__(THREADS, 1)
void chebnet_mma_kernel(
    const float* __restrict__ x,
    const float* __restrict__ b0, const float* __restrict__ b1,
    const float* __restrict__ b2, const float* __restrict__ b3,
    float* __restrict__ out)
{
    extern __shared__ char sm[];
    const uint32_t smb = s2u(sm);
    const int tid  = threadIdx.x;
    const int lane = tid & 31;
    const int warp = tid >> 5;
    const int row0 = blockIdx.x * 128 + warp * 16;
    const int r    = lane >> 2;        // 0..7
    const int q    = lane & 3;

    // ldmatrix per-lane byte offsets
    const uint32_t ofsB = ((uint32_t)(((lane & 7) + ((lane & 16) >> 1)) * SP) * 2) + ((lane & 8) * 2);
    const uint32_t ofsA = ((uint32_t)((lane & 15) * SP) * 2) + (lane & 16);
    const uint32_t scrW = smb + SCR_OFF + warp * WARP_SCR;

    // ---- load x -> warp scratch (hi/lo bf16, A-operand layout) ----
    {
        const bool v0 = (row0 + r)     < N_NODES;
        const bool v8 = (row0 + r + 8) < N_NODES;
        const float* xr0 = x + (size_t)(row0 + r) * DF;
        const float* xr8 = x + (size_t)(row0 + r + 8) * DF;
        char* s = sm + SCR_OFF + warp * WARP_SCR;
#pragma unroll
        for (int kt = 0; kt < 8; kt++) {
            const int c = kt * 16 + 2 * q;
            float2 e0 = v0 ? *(const float2*)(xr0 + c)     : make_float2(0.f, 0.f);
            float2 e1 = v8 ? *(const float2*)(xr8 + c)     : make_float2(0.f, 0.f);
            float2 e2 = v0 ? *(const float2*)(xr0 + c + 8) : make_float2(0.f, 0.f);
            float2 e3 = v8 ? *(const float2*)(xr8 + c + 8) : make_float2(0.f, 0.f);
            uint32_t h, lo;
            split2(e0.x, e0.y, h, lo);
            *(uint32_t*)(s + (r * SP + c) * 2) = h;
            *(uint32_t*)(s + SCR_HALF + (r * SP + c) * 2) = lo;
            split2(e1.x, e1.y, h, lo);
            *(uint32_t*)(s + ((r + 8) * SP + c) * 2) = h;
            *(uint32_t*)(s + SCR_HALF + ((r + 8) * SP + c) * 2) = lo;
            split2(e2.x, e2.y, h, lo);
            *(uint32_t*)(s + (r * SP + c + 8) * 2) = h;
            *(uint32_t*)(s + SCR_HALF + (r * SP + c + 8) * 2) = lo;
            split2(e3.x, e3.y, h, lo);
            *(uint32_t*)(s + ((r + 8) * SP + c + 8) * 2) = h;
            *(uint32_t*)(s + SCR_HALF + ((r + 8) * SP + c + 8) * 2) = lo;
        }
    }

    uint32_t Ahi[8][4], Alo[8][4];

    // ================= hidden layers 0..2 =================
    for (int l = 0; l < 3; l++) {
        __syncthreads();                       // prior readers of B done
        {   // copy this layer's padded weight image into smem B buffer
            const uint4* src = g_Wp4 + (size_t)l * LAYER_U4;
            uint4* dst = (uint4*)sm;
            for (int i = tid; i < LAYER_U4; i += THREADS) dst[i] = src[i];
        }
        __syncthreads();

        // reload A fragments from warp scratch
#pragma unroll
        for (int kt = 0; kt < 8; kt++) {
            const uint32_t aa = scrW + ofsA + kt * 32;
            LDSM4(Ahi[kt][0], Ahi[kt][1], Ahi[kt][2], Ahi[kt][3], aa);
            LDSM4(Alo[kt][0], Alo[kt][1], Alo[kt][2], Alo[kt][3], aa + SCR_HALF);
        }

        const float* bias = (l == 0) ? b0 : ((l == 1) ? b1 : b2);
        char* s = sm + SCR_OFF + warp * WARP_SCR;

#pragma unroll
        for (int p = 0; p < 8; p++) {          // n-tile pairs (nt=2p, 2p+1)
            const float2 bA = *(const float2*)(bias + 16 * p + 2 * q);
            const float2 bB = *(const float2*)(bias + 16 * p + 8 + 2 * q);
            float c0 = bA.x, c1 = bA.y, c2 = bA.x, c3 = bA.y;
            float c4 = bB.x, c5 = bB.y, c6 = bB.x, c7 = bB.y;
            const uint32_t pb = smb + (uint32_t)(p * 16 * SP) * 2 + ofsB;
#pragma unroll
            for (int kt = 0; kt < 8; kt++) {
                const uint32_t ba = pb + kt * 32;
                uint32_t h0, h1, h2, h3, l0, l1, l2, l3;
                LDSM4(h0, h1, h2, h3, ba);
                LDSM4(l0, l1, l2, l3, ba + HALF_BYTES);
                MMA(c0, c1, c2, c3, Ahi[kt][0], Ahi[kt][1], Ahi[kt][2], Ahi[kt][3], h0, h1);
                MMA(c4, c5, c6, c7, Ahi[kt][0], Ahi[kt][1], Ahi[kt][2], Ahi[kt][3], h2, h3);
                MMA(c0, c1, c2, c3, Ahi[kt][0], Ahi[kt][1], Ahi[kt][2], Ahi[kt][3], l0, l1);
                MMA(c4, c5, c6, c7, Ahi[kt][0], Ahi[kt][1], Ahi[kt][2], Ahi[kt][3], l2, l3);
                MMA(c0, c1, c2, c3, Alo[kt][0], Alo[kt][1], Alo[kt][2], Alo[kt][3], h0, h1);
                MMA(c4, c5, c6, c7, Alo[kt][0], Alo[kt][1], Alo[kt][2], Alo[kt][3], h2, h3);
            }
            // silu + split -> scratch (cols 16p..16p+15 == next layer k-tile p)
            const int ca = 16 * p + 2 * q, cb = ca + 8;
            uint32_t h, lo;
            split2(silu_f(c0), silu_f(c1), h, lo);
            *(uint32_t*)(s + (r * SP + ca) * 2) = h;
            *(uint32_t*)(s + SCR_HALF + (r * SP + ca) * 2) = lo;
            split2(silu_f(c2), silu_f(c3), h, lo);
            *(uint32_t*)(s + ((r + 8) * SP + ca) * 2) = h;
            *(uint32_t*)(s + SCR_HALF + ((r + 8) * SP + ca) * 2) = lo;
            split2(silu_f(c4), silu_f(c5), h, lo);
            *(uint32_t*)(s + (r * SP + cb) * 2) = h;
            *(uint32_t*)(s + SCR_HALF + (r * SP + cb) * 2) = lo;
            split2(silu_f(c6), silu_f(c7), h, lo);
            *(uint32_t*)(s + ((r + 8) * SP + cb) * 2) = h;
            *(uint32_t*)(s + SCR_HALF + ((r + 8) * SP + cb) * 2) = lo;
        }
    }

    // ================= output layer: N=40 (5 n-tiles) =================
    __syncthreads();
    {
        const uint4* src = g_Wp4 + (size_t)3 * LAYER_U4;
        uint4* dst = (uint4*)sm;
        for (int i = tid; i < LAYER_U4; i += THREADS) dst[i] = src[i];
    }
    __syncthreads();

#pragma unroll
    for (int kt = 0; kt < 8; kt++) {
        const uint32_t aa = scrW + ofsA + kt * 32;
        LDSM4(Ahi[kt][0], Ahi[kt][1], Ahi[kt][2], Ahi[kt][3], aa);
        LDSM4(Alo[kt][0], Alo[kt][1], Alo[kt][2], Alo[kt][3], aa + SCR_HALF);
    }

    float lgA[10], lgB[10];                    // rows r and r+8, 10 cols each
#pragma unroll
    for (int p = 0; p < 2; p++) {              // n-tiles 0..3
        const float2 bA = *(const float2*)(b3 + 16 * p + 2 * q);
        const float2 bB = *(const float2*)(b3 + 16 * p + 8 + 2 * q);
        float c0 = bA.x, c1 = bA.y, c2 = bA.x, c3 = bA.y;
        float c4 = bB.x, c5 = bB.y, c6 = bB.x, c7 = bB.y;
        const uint32_t pb = smb + (uint32_t)(p * 16 * SP) * 2 + ofsB;
#pragma unroll
        for (int kt = 0; kt < 8; kt++) {
            const uint32_t ba = pb + kt * 32;
            uint32_t h0, h1, h2, h3, l0, l1, l2, l3;
            LDSM4(h0, h1, h2, h3, ba);
            LDSM4(l0, l1, l2, l3, ba + HALF_BYTES);
            MMA(c0, c1, c2, c3, Ahi[kt][0], Ahi[kt][1], Ahi[kt][2], Ahi[kt][3], h0, h1);
            MMA(c4, c5, c6, c7, Ahi[kt][0], Ahi[kt][1], Ahi[kt][2], Ahi[kt][3], h2, h3);
            MMA(c0, c1, c2, c3, Ahi[kt][0], Ahi[kt][1], Ahi[kt][2], Ahi[kt][3], l0, l1);
            MMA(c4, c5, c6, c7, Ahi[kt][0], Ahi[kt][1], Ahi[kt][2], Ahi[kt][3], l2, l3);
            MMA(c0, c1, c2, c3, Alo[kt][0], Alo[kt][1], Alo[kt][2], Alo[kt][3], h0, h1);
            MMA(c4, c5, c6, c7, Alo[kt][0], Alo[kt][1], Alo[kt][2], Alo[kt][3], h2, h3);
        }
        lgA[4 * p + 0] = c0; lgA[4 * p + 1] = c1; lgB[4 * p + 0] = c2; lgB[4 * p + 1] = c3;
        lgA[4 * p + 2] = c4; lgA[4 * p + 3] = c5; lgB[4 * p + 2] = c6; lgB[4 * p + 3] = c7;
    }
    {   // n-tile 4 (cols 32..39)
        const float2 bA = *(const float2*)(b3 + 32 + 2 * q);
        float c0 = bA.x, c1 = bA.y, c2 = bA.x, c3 = bA.y;
        const int r2 = lane & 15;
        const uint32_t cb = smb + (uint32_t)((32 + (r2 & 7)) * SP) * 2 + (r2 & 8) * 2;
#pragma unroll
        for (int kt = 0; kt < 8; kt++) {
            const uint32_t ba = cb + kt * 32;
            uint32_t h0, h1, l0, l1;
            LDSM2(h0, h1, ba);
            LDSM2(l0, l1, ba + HALF_BYTES);
            MMA(c0, c1, c2, c3, Ahi[kt][0], Ahi[kt][1], Ahi[kt][2], Ahi[kt][3], h0, h1);
            MMA(c0, c1, c2, c3, Ahi[kt][0], Ahi[kt][1], Ahi[kt][2], Ahi[kt][3], l0, l1);
            MMA(c0, c1, c2, c3, Alo[kt][0], Alo[kt][1], Alo[kt][2], Alo[kt][3], h0, h1);
        }
        lgA[8] = c0; lgA[9] = c1; lgB[8] = c2; lgB[9] = c3;
    }

    // ---- log-softmax: quad reduction (lanes differing in bits 0,1 share a row)
    float mA = lgA[0], mB = lgB[0];
#pragma unroll
    for (int i = 1; i < 10; i++) { mA = fmaxf(mA, lgA[i]); mB = fmaxf(mB, lgB[i]); }
    mA = fmaxf(mA, __shfl_xor_sync(0xFFFFFFFF, mA, 1));
    mA = fmaxf(mA, __shfl_xor_sync(0xFFFFFFFF, mA, 2));
    mB = fmaxf(mB, __shfl_xor_sync(0xFFFFFFFF, mB, 1));
    mB = fmaxf(mB, __shfl_xor_sync(0xFFFFFFFF, mB, 2));
    float sA = 0.f, sB = 0.f;
#pragma unroll
    for (int i = 0; i < 10; i++) { sA += __expf(lgA[i] - mA); sB += __expf(lgB[i] - mB); }
    sA += __shfl_xor_sync(0xFFFFFFFF, sA, 1);
    sA += __shfl_xor_sync(0xFFFFFFFF, sA, 2);
    sB += __shfl_xor_sync(0xFFFFFFFF, sB, 1);
    sB += __shfl_xor_sync(0xFFFFFFFF, sB, 2);
    const float lseA = mA + __logf(sA);
    const float lseB = mB + __logf(sB);

    const int rA = row0 + r, rB = row0 + r + 8;
    if (rA < N_NODES) {
        float* o = out + (size_t)rA * NC + 2 * q;
#pragma unroll
        for (int nt = 0; nt < 5; nt++)
            *(float2*)(o + 8 * nt) = make_float2(lgA[2 * nt] - lseA, lgA[2 * nt + 1] - lseA);
    }
    if (rB < N_NODES) {
        float* o = out + (size_t)rB * NC + 2 * q;
#pragma unroll
        for (int nt = 0; nt < 5; nt++)
            *(float2*)(o + 8 * nt) = make_float2(lgB[2 * nt] - lseB, lgB[2 * nt + 1] - lseB);
    }
}

// ============================================================================
// Inputs: x, edge_index(dead), W0,b0, W1,b1, W2,b2, W3,b3
// ============================================================================
extern "C" void kernel_launch(void* const* d_in, const int* in_sizes, int n_in,
                              void* d_out, int out_size)
{
    (void)in_sizes; (void)n_in; (void)out_size;
    const float* x  = (const float*)d_in[0];
    const float* W0 = (const float*)d_in[2];
    const float* b0 = (const float*)d_in[3];
    const float* W1 = (const float*)d_in[4];
    const float* b1 = (const float*)d_in[5];
    const float* W2 = (const float*)d_in[6];
    const float* b2 = (const float*)d_in[7];
    const float* W3 = (const float*)d_in[8];
    const float* b3 = (const float*)d_in[9];
    float* out = (float*)d_out;

    cudaFuncSetAttribute(chebnet_mma_kernel,
                         cudaFuncAttributeMaxDynamicSharedMemorySize, SMEM_TOTAL);

    prep_weights<<<(4 * 128 * 128) / 256, 256>>>(W0, W1, W2, W3);
    chebnet_mma_kernel<<<NBLOCKS, THREADS, SMEM_TOTAL>>>(x, b0, b1, b2, b3, out);
}

// round 10
// speedup vs baseline: 1.7545x; 1.0692x over previous
#include <cuda_runtime.h>
#include <cuda_bf16.h>
#include <cstdint>

// ============================================================================
// ChebConvNet fused MLP via mma.sync (HMMA, baseline PTX).
//   h=silu(x@W0+b0); h=silu(h@W1+b1); h=silu(h@W2+b2); out=log_softmax(h@W3+b3)
// Each warp owns 32 rows as TWO 16-row sets with register-resident A fragments
// (hi+lo), so every B ldmatrix feeds 12 MMAs (4 accumulator chains) -> B smem
// traffic per row halves vs 16-row warps and HMMA latency is hidden by ILP.
// bf16 hi/lo 3-term split (AhiBhi + AhiBlo + AloBhi), fp32 accumulate.
// ============================================================================

#define N_NODES 200000
#define DF      128
#define NC      40
#define MB      256                         // rows per block
#define THREADS 256
#define NBLOCKS ((N_NODES + MB - 1) / MB)   // 782

#define SP 136                              // padded row stride (bf16 elems)
#define LAYER_U4 (2 * 128 * SP * 2 / 16)    // 4352 uint4 per layer (hi+lo)
#define HALF_BYTES (128 * SP * 2)           // 34816: lo offset inside B buffer
#define SCR_OFF    (2 * 128 * SP * 2)       // 69632: scratch after B buffer
#define WARP_SCR   (32 * SP * 2 * 2)        // 17408 bytes per warp (32 rows, hi+lo)
#define SCR_HALF   (32 * SP * 2)            // 8704: lo offset inside warp scratch
#define SCR_SET    (16 * SP * 2)            // 4352: row-set offset
#define SMEM_TOTAL (SCR_OFF + 8 * WARP_SCR) // 208896

// Prepped weights: per layer, [n:128][k:SP] bf16 hi then lo. L3 rows 40..127 = 0.
__device__ uint4 g_Wp4[4 * LAYER_U4];

__device__ __forceinline__ uint32_t s2u(const void* p) {
    uint32_t a;
    asm("{ .reg .u64 t; cvta.to.shared.u64 t, %1; cvt.u32.u64 %0, t; }" : "=r"(a) : "l"(p));
    return a;
}

#define LDSM4(r0, r1, r2, r3, a) \
    asm volatile("ldmatrix.sync.aligned.m8n8.x4.shared.b16 {%0,%1,%2,%3}, [%4];" \
                 : "=r"(r0), "=r"(r1), "=r"(r2), "=r"(r3) : "r"(a))
#define LDSM2(r0, r1, a) \
    asm volatile("ldmatrix.sync.aligned.m8n8.x2.shared.b16 {%0,%1}, [%2];" \
                 : "=r"(r0), "=r"(r1) : "r"(a))
#define MMA(c0, c1, c2, c3, a0, a1, a2, a3, b0, b1) \
    asm volatile("mma.sync.aligned.m16n8k16.row.col.f32.bf16.bf16.f32 " \
                 "{%0,%1,%2,%3}, {%4,%5,%6,%7}, {%8,%9}, {%0,%1,%2,%3};" \
                 : "+f"(c0), "+f"(c1), "+f"(c2), "+f"(c3) \
                 : "r"(a0), "r"(a1), "r"(a2), "r"(a3), "r"(b0), "r"(b1))

__device__ __forceinline__ uint32_t pkb(__nv_bfloat16 a, __nv_bfloat16 b) {
    return (uint32_t)__bfloat16_as_ushort(a) | ((uint32_t)__bfloat16_as_ushort(b) << 16);
}
__device__ __forceinline__ void split2(float a, float b, uint32_t& hi, uint32_t& lo) {
    __nv_bfloat16 ha = __float2bfloat16_rn(a), hb = __float2bfloat16_rn(b);
    hi = pkb(ha, hb);
    lo = pkb(__float2bfloat16_rn(a - __bfloat162float(ha)),
             __float2bfloat16_rn(b - __bfloat162float(hb)));
}
__device__ __forceinline__ float silu_f(float v) {
    return __fdividef(v, 1.0f + __expf(-v));
}

// ============================================================================
// Prep: W[k][n] -> padded [n][SP] bf16 hi/lo images (layer 3 zero-padded)
// ============================================================================
__global__ __launch_bounds__(256)
void prep_weights(const float* __restrict__ W0, const float* __restrict__ W1,
                  const float* __restrict__ W2, const float* __restrict__ W3) {
    int e = blockIdx.x * 256 + threadIdx.x;        // over 4*128*128
    if (e >= 4 * 128 * 128) return;
    int l = e >> 14, r = e & 16383, n = r >> 7, k = r & 127;
    float v;
    if (l < 3) {
        const float* W = (l == 0) ? W0 : ((l == 1) ? W1 : W2);
        v = W[k * 128 + n];
    } else {
        v = (n < NC) ? W3[k * NC + n] : 0.0f;
    }
    __nv_bfloat16* gw = (__nv_bfloat16*)g_Wp4;
    size_t base = (size_t)l * (2 * 128 * SP);
    __nv_bfloat16 h = __float2bfloat16_rn(v);
    gw[base + n * SP + k] = h;
    gw[base + 128 * SP + n * SP + k] = __float2bfloat16_rn(v - __bfloat162float(h));
}

// ============================================================================
// Main kernel: 8 warps x 32 rows (2 sets of 16); A fully register-resident.
// ============================================================================
__global__ __launch_bounds__(THREADS)
void chebnet_mma_kernel(
    const float* __restrict__ x,
    const float* __restrict__ b0, const float* __restrict__ b1,
    const float* __restrict__ b2, const float* __restrict__ b3,
    float* __restrict__ out)
{
    extern __shared__ char sm[];
    const uint32_t smb = s2u(sm);
    const int tid  = threadIdx.x;
    const int lane = tid & 31;
    const int warp = tid >> 5;
    const int row0 = blockIdx.x * MB + warp * 32;   // this warp's 32 rows
    const int r    = lane >> 2;        // 0..7
    const int q    = lane & 3;

    const uint32_t ofsB = ((uint32_t)(((lane & 7) + ((lane & 16) >> 1)) * SP) * 2) + ((lane & 8) * 2);
    const uint32_t ofsA = ((uint32_t)((lane & 15) * SP) * 2) + (lane & 16);
    const uint32_t scrW = smb + SCR_OFF + warp * WARP_SCR;
    char* scrP = sm + SCR_OFF + warp * WARP_SCR;

    // ---- load x -> warp scratch (hi/lo bf16, A-operand layout), both sets ----
#pragma unroll
    for (int s = 0; s < 2; s++) {
        const int rb = s * 16;
        const bool v0 = (row0 + rb + r)     < N_NODES;
        const bool v8 = (row0 + rb + r + 8) < N_NODES;
        const float* xr0 = x + (size_t)(row0 + rb + r) * DF;
        const float* xr8 = x + (size_t)(row0 + rb + r + 8) * DF;
#pragma unroll
        for (int kt = 0; kt < 8; kt++) {
            const int c = kt * 16 + 2 * q;
            float2 e0 = v0 ? *(const float2*)(xr0 + c)     : make_float2(0.f, 0.f);
            float2 e1 = v8 ? *(const float2*)(xr8 + c)     : make_float2(0.f, 0.f);
            float2 e2 = v0 ? *(const float2*)(xr0 + c + 8) : make_float2(0.f, 0.f);
            float2 e3 = v8 ? *(const float2*)(xr8 + c + 8) : make_float2(0.f, 0.f);
            uint32_t h, lo;
            split2(e0.x, e0.y, h, lo);
            *(uint32_t*)(scrP + ((rb + r) * SP + c) * 2) = h;
            *(uint32_t*)(scrP + SCR_HALF + ((rb + r) * SP + c) * 2) = lo;
            split2(e1.x, e1.y, h, lo);
            *(uint32_t*)(scrP + ((rb + r + 8) * SP + c) * 2) = h;
            *(uint32_t*)(scrP + SCR_HALF + ((rb + r + 8) * SP + c) * 2) = lo;
            split2(e2.x, e2.y, h, lo);
            *(uint32_t*)(scrP + ((rb + r) * SP + c + 8) * 2) = h;
            *(uint32_t*)(scrP + SCR_HALF + ((rb + r) * SP + c + 8) * 2) = lo;
            split2(e3.x, e3.y, h, lo);
            *(uint32_t*)(scrP + ((rb + r + 8) * SP + c + 8) * 2) = h;
            *(uint32_t*)(scrP + SCR_HALF + ((rb + r + 8) * SP + c + 8) * 2) = lo;
        }
    }

    uint32_t Ahi[2][8][4], Alo[2][8][4];

    // ================= hidden layers 0..2 =================
    for (int l = 0; l < 3; l++) {
        __syncthreads();                       // all readers of old B done
        {   // copy layer's padded weight image into smem B buffer
            const uint4* src = g_Wp4 + (size_t)l * LAYER_U4;
            uint4* dst = (uint4*)sm;
            for (int i = tid; i < LAYER_U4; i += THREADS) dst[i] = src[i];
        }
        __syncthreads();

        // load A fragments (both sets) from warp scratch
#pragma unroll
        for (int s = 0; s < 2; s++)
#pragma unroll
            for (int kt = 0; kt < 8; kt++) {
                const uint32_t aa = scrW + s * SCR_SET + ofsA + kt * 32;
                LDSM4(Ahi[s][kt][0], Ahi[s][kt][1], Ahi[s][kt][2], Ahi[s][kt][3], aa);
                LDSM4(Alo[s][kt][0], Alo[s][kt][1], Alo[s][kt][2], Alo[s][kt][3], aa + SCR_HALF);
            }

        const float* bias = (l == 0) ? b0 : ((l == 1) ? b1 : b2);

#pragma unroll
        for (int p = 0; p < 8; p++) {          // n-tile pairs (cols 16p..16p+15)
            const float2 bA = *(const float2*)(bias + 16 * p + 2 * q);
            const float2 bB = *(const float2*)(bias + 16 * p + 8 + 2 * q);
            float c[2][8];
#pragma unroll
            for (int s = 0; s < 2; s++) {
                c[s][0] = bA.x; c[s][1] = bA.y; c[s][2] = bA.x; c[s][3] = bA.y;
                c[s][4] = bB.x; c[s][5] = bB.y; c[s][6] = bB.x; c[s][7] = bB.y;
            }
            const uint32_t pb = smb + (uint32_t)(p * 16 * SP) * 2 + ofsB;
#pragma unroll
            for (int kt = 0; kt < 8; kt++) {
                const uint32_t ba = pb + kt * 32;
                uint32_t h0, h1, h2, h3, l0, l1, l2, l3;
                LDSM4(h0, h1, h2, h3, ba);
                LDSM4(l0, l1, l2, l3, ba + HALF_BYTES);
                // 12 MMAs, 4 independent chains round-robin (dep distance 4)
                MMA(c[0][0], c[0][1], c[0][2], c[0][3], Ahi[0][kt][0], Ahi[0][kt][1], Ahi[0][kt][2], Ahi[0][kt][3], h0, h1);
                MMA(c[0][4], c[0][5], c[0][6], c[0][7], Ahi[0][kt][0], Ahi[0][kt][1], Ahi[0][kt][2], Ahi[0][kt][3], h2, h3);
                MMA(c[1][0], c[1][1], c[1][2], c[1][3], Ahi[1][kt][0], Ahi[1][kt][1], Ahi[1][kt][2], Ahi[1][kt][3], h0, h1);
                MMA(c[1][4], c[1][5], c[1][6], c[1][7], Ahi[1][kt][0], Ahi[1][kt][1], Ahi[1][kt][2], Ahi[1][kt][3], h2, h3);
                MMA(c[0][0], c[0][1], c[0][2], c[0][3], Ahi[0][kt][0], Ahi[0][kt][1], Ahi[0][kt][2], Ahi[0][kt][3], l0, l1);
                MMA(c[0][4], c[0][5], c[0][6], c[0][7], Ahi[0][kt][0], Ahi[0][kt][1], Ahi[0][kt][2], Ahi[0][kt][3], l2, l3);
                MMA(c[1][0], c[1][1], c[1][2], c[1][3], Ahi[1][kt][0], Ahi[1][kt][1], Ahi[1][kt][2], Ahi[1][kt][3], l0, l1);
                MMA(c[1][4], c[1][5], c[1][6], c[1][7], Ahi[1][kt][0], Ahi[1][kt][1], Ahi[1][kt][2], Ahi[1][kt][3], l2, l3);
                MMA(c[0][0], c[0][1], c[0][2], c[0][3], Alo[0][kt][0], Alo[0][kt][1], Alo[0][kt][2], Alo[0][kt][3], h0, h1);
                MMA(c[0][4], c[0][5], c[0][6], c[0][7], Alo[0][kt][0], Alo[0][kt][1], Alo[0][kt][2], Alo[0][kt][3], h2, h3);
                MMA(c[1][0], c[1][1], c[1][2], c[1][3], Alo[1][kt][0], Alo[1][kt][1], Alo[1][kt][2], Alo[1][kt][3], h0, h1);
                MMA(c[1][4], c[1][5], c[1][6], c[1][7], Alo[1][kt][0], Alo[1][kt][1], Alo[1][kt][2], Alo[1][kt][3], h2, h3);
            }
            // silu + split -> scratch (cols 16p..16p+15 == next layer k-tile p)
            const int ca = 16 * p + 2 * q, cb = ca + 8;
#pragma unroll
            for (int s = 0; s < 2; s++) {
                const int rb = s * 16;
                uint32_t h, lo;
                split2(silu_f(c[s][0]), silu_f(c[s][1]), h, lo);
                *(uint32_t*)(scrP + ((rb + r) * SP + ca) * 2) = h;
                *(uint32_t*)(scrP + SCR_HALF + ((rb + r) * SP + ca) * 2) = lo;
                split2(silu_f(c[s][2]), silu_f(c[s][3]), h, lo);
                *(uint32_t*)(scrP + ((rb + r + 8) * SP + ca) * 2) = h;
                *(uint32_t*)(scrP + SCR_HALF + ((rb + r + 8) * SP + ca) * 2) = lo;
                split2(silu_f(c[s][4]), silu_f(c[s][5]), h, lo);
                *(uint32_t*)(scrP + ((rb + r) * SP + cb) * 2) = h;
                *(uint32_t*)(scrP + SCR_HALF + ((rb + r) * SP + cb) * 2) = lo;
                split2(silu_f(c[s][6]), silu_f(c[s][7]), h, lo);
                *(uint32_t*)(scrP + ((rb + r + 8) * SP + cb) * 2) = h;
                *(uint32_t*)(scrP + SCR_HALF + ((rb + r + 8) * SP + cb) * 2) = lo;
            }
        }
    }

    // ================= output layer: N=40 =================
    __syncthreads();
    {
        const uint4* src = g_Wp4 + (size_t)3 * LAYER_U4;
        uint4* dst = (uint4*)sm;
        for (int i = tid; i < LAYER_U4; i += THREADS) dst[i] = src[i];
    }
    __syncthreads();

#pragma unroll
    for (int s = 0; s < 2; s++)
#pragma unroll
        for (int kt = 0; kt < 8; kt++) {
            const uint32_t aa = scrW + s * SCR_SET + ofsA + kt * 32;
            LDSM4(Ahi[s][kt][0], Ahi[s][kt][1], Ahi[s][kt][2], Ahi[s][kt][3], aa);
            LDSM4(Alo[s][kt][0], Alo[s][kt][1], Alo[s][kt][2], Alo[s][kt][3], aa + SCR_HALF);
        }

#pragma unroll
    for (int s = 0; s < 2; s++) {
        float lgA[10], lgB[10];                // rows rb+r and rb+r+8
#pragma unroll
        for (int p = 0; p < 2; p++) {          // n-tiles 0..3
            const float2 bA = *(const float2*)(b3 + 16 * p + 2 * q);
            const float2 bB = *(const float2*)(b3 + 16 * p + 8 + 2 * q);
            float c0 = bA.x, c1 = bA.y, c2 = bA.x, c3 = bA.y;
            float c4 = bB.x, c5 = bB.y, c6 = bB.x, c7 = bB.y;
            const uint32_t pb = smb + (uint32_t)(p * 16 * SP) * 2 + ofsB;
#pragma unroll
            for (int kt = 0; kt < 8; kt++) {
                const uint32_t ba = pb + kt * 32;
                uint32_t h0, h1, h2, h3, l0, l1, l2, l3;
                LDSM4(h0, h1, h2, h3, ba);
                LDSM4(l0, l1, l2, l3, ba + HALF_BYTES);
                MMA(c0, c1, c2, c3, Ahi[s][kt][0], Ahi[s][kt][1], Ahi[s][kt][2], Ahi[s][kt][3], h0, h1);
                MMA(c4, c5, c6, c7, Ahi[s][kt][0], Ahi[s][kt][1], Ahi[s][kt][2], Ahi[s][kt][3], h2, h3);
                MMA(c0, c1, c2, c3, Ahi[s][kt][0], Ahi[s][kt][1], Ahi[s][kt][2], Ahi[s][kt][3], l0, l1);
                MMA(c4, c5, c6, c7, Ahi[s][kt][0], Ahi[s][kt][1], Ahi[s][kt][2], Ahi[s][kt][3], l2, l3);
                MMA(c0, c1, c2, c3, Alo[s][kt][0], Alo[s][kt][1], Alo[s][kt][2], Alo[s][kt][3], h0, h1);
                MMA(c4, c5, c6, c7, Alo[s][kt][0], Alo[s][kt][1], Alo[s][kt][2], Alo[s][kt][3], h2, h3);
            }
            lgA[4 * p + 0] = c0; lgA[4 * p + 1] = c1; lgB[4 * p + 0] = c2; lgB[4 * p + 1] = c3;
            lgA[4 * p + 2] = c4; lgA[4 * p + 3] = c5; lgB[4 * p + 2] = c6; lgB[4 * p + 3] = c7;
        }
        {   // n-tile 4 (cols 32..39)
            const float2 bA = *(const float2*)(b3 + 32 + 2 * q);
            float c0 = bA.x, c1 = bA.y, c2 = bA.x, c3 = bA.y;
            const int r2 = lane & 15;
            const uint32_t cb = smb + (uint32_t)((32 + (r2 & 7)) * SP) * 2 + (r2 & 8) * 2;
#pragma unroll
            for (int kt = 0; kt < 8; kt++) {
                const uint32_t ba = cb + kt * 32;
                uint32_t h0, h1, l0, l1;
                LDSM2(h0, h1, ba);
                LDSM2(l0, l1, ba + HALF_BYTES);
                MMA(c0, c1, c2, c3, Ahi[s][kt][0], Ahi[s][kt][1], Ahi[s][kt][2], Ahi[s][kt][3], h0, h1);
                MMA(c0, c1, c2, c3, Ahi[s][kt][0], Ahi[s][kt][1], Ahi[s][kt][2], Ahi[s][kt][3], l0, l1);
                MMA(c0, c1, c2, c3, Alo[s][kt][0], Alo[s][kt][1], Alo[s][kt][2], Alo[s][kt][3], h0, h1);
            }
            lgA[8] = c0; lgA[9] = c1; lgB[8] = c2; lgB[9] = c3;
        }

        // ---- log-softmax: quad reduction (lanes differing in bits 0,1) ----
        float mA = lgA[0], mB = lgB[0];
#pragma unroll
        for (int i = 1; i < 10; i++) { mA = fmaxf(mA, lgA[i]); mB = fmaxf(mB, lgB[i]); }
        mA = fmaxf(mA, __shfl_xor_sync(0xFFFFFFFF, mA, 1));
        mA = fmaxf(mA, __shfl_xor_sync(0xFFFFFFFF, mA, 2));
        mB = fmaxf(mB, __shfl_xor_sync(0xFFFFFFFF, mB, 1));
        mB = fmaxf(mB, __shfl_xor_sync(0xFFFFFFFF, mB, 2));
        float sA = 0.f, sB = 0.f;
#pragma unroll
        for (int i = 0; i < 10; i++) { sA += __expf(lgA[i] - mA); sB += __expf(lgB[i] - mB); }
        sA += __shfl_xor_sync(0xFFFFFFFF, sA, 1);
        sA += __shfl_xor_sync(0xFFFFFFFF, sA, 2);
        sB += __shfl_xor_sync(0xFFFFFFFF, sB, 1);
        sB += __shfl_xor_sync(0xFFFFFFFF, sB, 2);
        const float lseA = mA + __logf(sA);
        const float lseB = mB + __logf(sB);

        const int rb = s * 16;
        const int rA = row0 + rb + r, rB = row0 + rb + r + 8;
        if (rA < N_NODES) {
            float* o = out + (size_t)rA * NC + 2 * q;
#pragma unroll
            for (int nt = 0; nt < 5; nt++)
                *(float2*)(o + 8 * nt) = make_float2(lgA[2 * nt] - lseA, lgA[2 * nt + 1] - lseA);
        }
        if (rB < N_NODES) {
            float* o = out + (size_t)rB * NC + 2 * q;
#pragma unroll
            for (int nt = 0; nt < 5; nt++)
                *(float2*)(o + 8 * nt) = make_float2(lgB[2 * nt] - lseB, lgB[2 * nt + 1] - lseB);
        }
    }
}

// ============================================================================
// Inputs: x, edge_index(dead), W0,b0, W1,b1, W2,b2, W3,b3
// ============================================================================
extern "C" void kernel_launch(void* const* d_in, const int* in_sizes, int n_in,
                              void* d_out, int out_size)
{
    (void)in_sizes; (void)n_in; (void)out_size;
    const float* x  = (const float*)d_in[0];
    const float* W0 = (const float*)d_in[2];
    const float* b0 = (const float*)d_in[3];
    const float* W1 = (const float*)d_in[4];
    const float* b1 = (const float*)d_in[5];
    const float* W2 = (const float*)d_in[6];
    const float* b2 = (const float*)d_in[7];
    const float* W3 = (const float*)d_in[8];
    const float* b3 = (const float*)d_in[9];
    float* out = (float*)d_out;

    cudaFuncSetAttribute(chebnet_mma_kernel,
                         cudaFuncAttributeMaxDynamicSharedMemorySize, SMEM_TOTAL);

    prep_weights<<<(4 * 128 * 128) / 256, 256>>>(W0, W1, W2, W3);
    chebnet_mma_kernel<<<NBLOCKS, THREADS, SMEM_TOTAL>>>(x, b0, b1, b2, b3, out);
}

// round 11
// speedup vs baseline: 2.3380x; 1.3325x over previous
#include <cuda_runtime.h>
#include <cuda_bf16.h>
#include <cstdint>

// ============================================================================
// ChebConvNet fused MLP via mma.sync (HMMA, baseline PTX).
//   h=silu(x@W0+b0); h=silu(h@W1+b1); h=silu(h@W2+b2); out=log_softmax(h@W3+b3)
// Register-chained: m16n8k16 C-frag layout == A-frag layout, so SiLU'd outputs
// are re-packed (hi/lo bf16) directly into next layer's A fragments in
// registers -- zero smem traffic for activations. Weights double-buffered in
// smem via cp.async, prefetched during the previous layer's MMAs.
// bf16 hi/lo 3-term split (AhiBhi + AhiBlo + AloBhi), fp32 accumulate.
// 384 threads (12 warps) x 16 rows/warp = 192 rows/block.
// ============================================================================

#define N_NODES 200000
#define DF      128
#define NC      40
#define THREADS 384
#define MB      192
#define NBLOCKS ((N_NODES + MB - 1) / MB)   // 1042

#define SP 136                              // padded row stride (bf16 elems)
#define IMG_BYTES  (2 * 128 * SP * 2)       // 69632: one layer image (hi+lo)
#define LAYER_U4   (IMG_BYTES / 16)         // 4352
#define HALF_BYTES (128 * SP * 2)           // 34816: lo offset inside image
#define SMEM_TOTAL (2 * IMG_BYTES)          // 139264: double-buffered weights

// Prepped weights: per layer, [n:128][k:SP] bf16 hi then lo. L3 rows 40..127=0.
__device__ uint4 g_Wp4[4 * LAYER_U4];

__device__ __forceinline__ uint32_t s2u(const void* p) {
    uint32_t a;
    asm("{ .reg .u64 t; cvta.to.shared.u64 t, %1; cvt.u32.u64 %0, t; }" : "=r"(a) : "l"(p));
    return a;
}

#define LDSM4(r0, r1, r2, r3, a) \
    asm volatile("ldmatrix.sync.aligned.m8n8.x4.shared.b16 {%0,%1,%2,%3}, [%4];" \
                 : "=r"(r0), "=r"(r1), "=r"(r2), "=r"(r3) : "r"(a))
#define LDSM2(r0, r1, a) \
    asm volatile("ldmatrix.sync.aligned.m8n8.x2.shared.b16 {%0,%1}, [%2];" \
                 : "=r"(r0), "=r"(r1) : "r"(a))
#define MMA(c0, c1, c2, c3, a0, a1, a2, a3, b0, b1) \
    asm volatile("mma.sync.aligned.m16n8k16.row.col.f32.bf16.bf16.f32 " \
                 "{%0,%1,%2,%3}, {%4,%5,%6,%7}, {%8,%9}, {%0,%1,%2,%3};" \
                 : "+f"(c0), "+f"(c1), "+f"(c2), "+f"(c3) \
                 : "r"(a0), "r"(a1), "r"(a2), "r"(a3), "r"(b0), "r"(b1))

#define CP_ASYNC16(dst, src) \
    asm volatile("cp.async.cg.shared.global [%0], [%1], 16;" \
                 :: "r"(dst), "l"(src) : "memory")
#define CP_COMMIT() asm volatile("cp.async.commit_group;" ::: "memory")
#define CP_WAIT1()  asm volatile("cp.async.wait_group 1;" ::: "memory")
#define CP_WAIT0()  asm volatile("cp.async.wait_group 0;" ::: "memory")

__device__ __forceinline__ uint32_t pkb(__nv_bfloat16 a, __nv_bfloat16 b) {
    return (uint32_t)__bfloat16_as_ushort(a) | ((uint32_t)__bfloat16_as_ushort(b) << 16);
}
__device__ __forceinline__ void split2(float a, float b, uint32_t& hi, uint32_t& lo) {
    __nv_bfloat16 ha = __float2bfloat16_rn(a), hb = __float2bfloat16_rn(b);
    hi = pkb(ha, hb);
    lo = pkb(__float2bfloat16_rn(a - __bfloat162float(ha)),
             __float2bfloat16_rn(b - __bfloat162float(hb)));
}
__device__ __forceinline__ float silu_f(float v) {
    return __fdividef(v, 1.0f + __expf(-v));
}

// ============================================================================
// Prep: W[k][n] -> padded [n][SP] bf16 hi/lo images (layer 3 zero-padded)
// ============================================================================
__global__ __launch_bounds__(256)
void prep_weights(const float* __restrict__ W0, const float* __restrict__ W1,
                  const float* __restrict__ W2, const float* __restrict__ W3) {
    int e = blockIdx.x * 256 + threadIdx.x;        // over 4*128*128
    if (e >= 4 * 128 * 128) return;
    int l = e >> 14, r = e & 16383, n = r >> 7, k = r & 127;
    float v;
    if (l < 3) {
        const float* W = (l == 0) ? W0 : ((l == 1) ? W1 : W2);
        v = W[k * 128 + n];
    } else {
        v = (n < NC) ? W3[k * NC + n] : 0.0f;
    }
    __nv_bfloat16* gw = (__nv_bfloat16*)g_Wp4;
    size_t base = (size_t)l * (2 * 128 * SP);
    __nv_bfloat16 h = __float2bfloat16_rn(v);
    gw[base + n * SP + k] = h;
    gw[base + 128 * SP + n * SP + k] = __float2bfloat16_rn(v - __bfloat162float(h));
}

// async-copy one layer image into a smem buffer
__device__ __forceinline__ void cpasync_layer(uint32_t dst, int layer, int tid) {
    const uint4* src = g_Wp4 + (size_t)layer * LAYER_U4;
    for (int i = tid; i < LAYER_U4; i += THREADS)
        CP_ASYNC16(dst + (uint32_t)i * 16, src + i);
    CP_COMMIT();
}

// one hidden layer: old A (hi/lo regs) x B(smem) -> silu -> new A (hi/lo regs)
__device__ __forceinline__ void hidden_layer(
    const uint32_t Ahi[8][4], const uint32_t Alo[8][4],
    uint32_t nAhi[8][4], uint32_t nAlo[8][4],
    uint32_t bufbase, const float* __restrict__ bias,
    uint32_t ofsB, int q)
{
#pragma unroll
    for (int p = 0; p < 8; p++) {              // n-tile pairs (cols 16p..16p+15)
        const float2 bA = __ldg((const float2*)(bias + 16 * p + 2 * q));
        const float2 bB = __ldg((const float2*)(bias + 16 * p + 8 + 2 * q));
        float c0 = bA.x, c1 = bA.y, c2 = bA.x, c3 = bA.y;
        float c4 = bB.x, c5 = bB.y, c6 = bB.x, c7 = bB.y;
        const uint32_t pb = bufbase + (uint32_t)(p * 16 * SP) * 2 + ofsB;
#pragma unroll
        for (int kt = 0; kt < 8; kt++) {
            const uint32_t ba = pb + kt * 32;
            uint32_t h0, h1, h2, h3, l0, l1, l2, l3;
            LDSM4(h0, h1, h2, h3, ba);
            LDSM4(l0, l1, l2, l3, ba + HALF_BYTES);
            MMA(c0, c1, c2, c3, Ahi[kt][0], Ahi[kt][1], Ahi[kt][2], Ahi[kt][3], h0, h1);
            MMA(c4, c5, c6, c7, Ahi[kt][0], Ahi[kt][1], Ahi[kt][2], Ahi[kt][3], h2, h3);
            MMA(c0, c1, c2, c3, Ahi[kt][0], Ahi[kt][1], Ahi[kt][2], Ahi[kt][3], l0, l1);
            MMA(c4, c5, c6, c7, Ahi[kt][0], Ahi[kt][1], Ahi[kt][2], Ahi[kt][3], l2, l3);
            MMA(c0, c1, c2, c3, Alo[kt][0], Alo[kt][1], Alo[kt][2], Alo[kt][3], h0, h1);
            MMA(c4, c5, c6, c7, Alo[kt][0], Alo[kt][1], Alo[kt][2], Alo[kt][3], h2, h3);
        }
        // C-frag == A-frag: silu + hi/lo split -> next layer k-tile p fragments
        split2(silu_f(c0), silu_f(c1), nAhi[p][0], nAlo[p][0]);
        split2(silu_f(c2), silu_f(c3), nAhi[p][1], nAlo[p][1]);
        split2(silu_f(c4), silu_f(c5), nAhi[p][2], nAlo[p][2]);
        split2(silu_f(c6), silu_f(c7), nAhi[p][3], nAlo[p][3]);
    }
}

// ============================================================================
// Main kernel
// ============================================================================
__global__ __launch_bounds__(THREADS)
void chebnet_mma_kernel(
    const float* __restrict__ x,
    const float* __restrict__ b0, const float* __restrict__ b1,
    const float* __restrict__ b2, const float* __restrict__ b3,
    float* __restrict__ out)
{
    extern __shared__ char sm[];
    const uint32_t smb = s2u(sm);
    const int tid  = threadIdx.x;
    const int lane = tid & 31;
    const int warp = tid >> 5;
    const int row0 = blockIdx.x * MB + warp * 16;   // this warp's 16 rows
    const int r    = lane >> 2;        // 0..7
    const int q    = lane & 3;

    const uint32_t ofsB = ((uint32_t)(((lane & 7) + ((lane & 16) >> 1)) * SP) * 2) + ((lane & 8) * 2);

    // ---- prefetch weights: L0 -> buf0 (G0), L1 -> buf1 (G1) ----
    cpasync_layer(smb, 0, tid);
    cpasync_layer(smb + IMG_BYTES, 1, tid);

    // ---- load x directly into A fragments (hi/lo), overlapped with copies ----
    uint32_t AhiA[8][4], AloA[8][4], AhiB[8][4], AloB[8][4];
    {
        const bool v0 = (row0 + r)     < N_NODES;
        const bool v8 = (row0 + r + 8) < N_NODES;
        const float* xr0 = x + (size_t)(row0 + r) * DF;
        const float* xr8 = x + (size_t)(row0 + r + 8) * DF;
#pragma unroll
        for (int kt = 0; kt < 8; kt++) {
            const int c = kt * 16 + 2 * q;
            float2 e0 = v0 ? *(const float2*)(xr0 + c)     : make_float2(0.f, 0.f);
            float2 e1 = v8 ? *(const float2*)(xr8 + c)     : make_float2(0.f, 0.f);
            float2 e2 = v0 ? *(const float2*)(xr0 + c + 8) : make_float2(0.f, 0.f);
            float2 e3 = v8 ? *(const float2*)(xr8 + c + 8) : make_float2(0.f, 0.f);
            split2(e0.x, e0.y, AhiA[kt][0], AloA[kt][0]);
            split2(e1.x, e1.y, AhiA[kt][1], AloA[kt][1]);
            split2(e2.x, e2.y, AhiA[kt][2], AloA[kt][2]);
            split2(e3.x, e3.y, AhiA[kt][3], AloA[kt][3]);
        }
    }

    // ---- layer 0 (buf0) ----
    CP_WAIT1();                 // G0 (L0) landed
    __syncthreads();
    hidden_layer(AhiA, AloA, AhiB, AloB, smb, b0, ofsB, q);
    __syncthreads();            // all warps done reading buf0
    cpasync_layer(smb, 2, tid); // G2: L2 -> buf0

    // ---- layer 1 (buf1) ----
    CP_WAIT1();                 // G1 (L1) landed
    __syncthreads();
    hidden_layer(AhiB, AloB, AhiA, AloA, smb + IMG_BYTES, b1, ofsB, q);
    __syncthreads();            // all warps done reading buf1
    cpasync_layer(smb + IMG_BYTES, 3, tid);  // G3: L3 -> buf1

    // ---- layer 2 (buf0) ----
    CP_WAIT1();                 // G2 (L2) landed
    __syncthreads();
    hidden_layer(AhiA, AloA, AhiB, AloB, smb, b2, ofsB, q);

    // ---- output layer (buf1): N=40 ----
    CP_WAIT0();                 // G3 (L3) landed
    __syncthreads();
    {
        const uint32_t bufb = smb + IMG_BYTES;
        float lgA[10], lgB[10];            // rows r and r+8, 10 cols each
#pragma unroll
        for (int p = 0; p < 2; p++) {      // n-tiles 0..3 (cols 0..31)
            const float2 bA = __ldg((const float2*)(b3 + 16 * p + 2 * q));
            const float2 bB = __ldg((const float2*)(b3 + 16 * p + 8 + 2 * q));
            float c0 = bA.x, c1 = bA.y, c2 = bA.x, c3 = bA.y;
            float c4 = bB.x, c5 = bB.y, c6 = bB.x, c7 = bB.y;
            const uint32_t pb = bufb + (uint32_t)(p * 16 * SP) * 2 + ofsB;
#pragma unroll
            for (int kt = 0; kt < 8; kt++) {
                const uint32_t ba = pb + kt * 32;
                uint32_t h0, h1, h2, h3, l0, l1, l2, l3;
                LDSM4(h0, h1, h2, h3, ba);
                LDSM4(l0, l1, l2, l3, ba + HALF_BYTES);
                MMA(c0, c1, c2, c3, AhiB[kt][0], AhiB[kt][1], AhiB[kt][2], AhiB[kt][3], h0, h1);
                MMA(c4, c5, c6, c7, AhiB[kt][0], AhiB[kt][1], AhiB[kt][2], AhiB[kt][3], h2, h3);
                MMA(c0, c1, c2, c3, AhiB[kt][0], AhiB[kt][1], AhiB[kt][2], AhiB[kt][3], l0, l1);
                MMA(c4, c5, c6, c7, AhiB[kt][0], AhiB[kt][1], AhiB[kt][2], AhiB[kt][3], l2, l3);
                MMA(c0, c1, c2, c3, AloB[kt][0], AloB[kt][1], AloB[kt][2], AloB[kt][3], h0, h1);
                MMA(c4, c5, c6, c7, AloB[kt][0], AloB[kt][1], AloB[kt][2], AloB[kt][3], h2, h3);
            }
            lgA[4 * p + 0] = c0; lgA[4 * p + 1] = c1; lgB[4 * p + 0] = c2; lgB[4 * p + 1] = c3;
            lgA[4 * p + 2] = c4; lgA[4 * p + 3] = c5; lgB[4 * p + 2] = c6; lgB[4 * p + 3] = c7;
        }
        {   // n-tile 4 (cols 32..39)
            const float2 bA = __ldg((const float2*)(b3 + 32 + 2 * q));
            float c0 = bA.x, c1 = bA.y, c2 = bA.x, c3 = bA.y;
            const int r2 = lane & 15;
            const uint32_t cb = bufb + (uint32_t)((32 + (r2 & 7)) * SP) * 2 + (r2 & 8) * 2;
#pragma unroll
            for (int kt = 0; kt < 8; kt++) {
                const uint32_t ba = cb + kt * 32;
                uint32_t h0, h1, l0, l1;
                LDSM2(h0, h1, ba);
                LDSM2(l0, l1, ba + HALF_BYTES);
                MMA(c0, c1, c2, c3, AhiB[kt][0], AhiB[kt][1], AhiB[kt][2], AhiB[kt][3], h0, h1);
                MMA(c0, c1, c2, c3, AhiB[kt][0], AhiB[kt][1], AhiB[kt][2], AhiB[kt][3], l0, l1);
                MMA(c0, c1, c2, c3, AloB[kt][0], AloB[kt][1], AloB[kt][2], AloB[kt][3], h0, h1);
            }
            lgA[8] = c0; lgA[9] = c1; lgB[8] = c2; lgB[9] = c3;
        }

        // ---- log-softmax: quad reduction (lanes differing in bits 0,1) ----
        float mA = lgA[0], mB = lgB[0];
#pragma unroll
        for (int i = 1; i < 10; i++) { mA = fmaxf(mA, lgA[i]); mB = fmaxf(mB, lgB[i]); }
        mA = fmaxf(mA, __shfl_xor_sync(0xFFFFFFFF, mA, 1));
        mA = fmaxf(mA, __shfl_xor_sync(0xFFFFFFFF, mA, 2));
        mB = fmaxf(mB, __shfl_xor_sync(0xFFFFFFFF, mB, 1));
        mB = fmaxf(mB, __shfl_xor_sync(0xFFFFFFFF, mB, 2));
        float sA = 0.f, sB = 0.f;
#pragma unroll
        for (int i = 0; i < 10; i++) { sA += __expf(lgA[i] - mA); sB += __expf(lgB[i] - mB); }
        sA += __shfl_xor_sync(0xFFFFFFFF, sA, 1);
        sA += __shfl_xor_sync(0xFFFFFFFF, sA, 2);
        sB += __shfl_xor_sync(0xFFFFFFFF, sB, 1);
        sB += __shfl_xor_sync(0xFFFFFFFF, sB, 2);
        const float lseA = mA + __logf(sA);
        const float lseB = mB + __logf(sB);

        const int rA = row0 + r, rB = row0 + r + 8;
        if (rA < N_NODES) {
            float* o = out + (size_t)rA * NC + 2 * q;
#pragma unroll
            for (int nt = 0; nt < 5; nt++)
                *(float2*)(o + 8 * nt) = make_float2(lgA[2 * nt] - lseA, lgA[2 * nt + 1] - lseA);
        }
        if (rB < N_NODES) {
            float* o = out + (size_t)rB * NC + 2 * q;
#pragma unroll
            for (int nt = 0; nt < 5; nt++)
                *(float2*)(o + 8 * nt) = make_float2(lgB[2 * nt] - lseB, lgB[2 * nt + 1] - lseB);
        }
    }
}

// ============================================================================
// Inputs: x, edge_index(dead), W0,b0, W1,b1, W2,b2, W3,b3
// ============================================================================
extern "C" void kernel_launch(void* const* d_in, const int* in_sizes, int n_in,
                              void* d_out, int out_size)
{
    (void)in_sizes; (void)n_in; (void)out_size;
    const float* x  = (const float*)d_in[0];
    const float* W0 = (const float*)d_in[2];
    const float* b0 = (const float*)d_in[3];
    const float* W1 = (const float*)d_in[4];
    const float* b1 = (const float*)d_in[5];
    const float* W2 = (const float*)d_in[6];
    const float* b2 = (const float*)d_in[7];
    const float* W3 = (const float*)d_in[8];
    const float* b3 = (const float*)d_in[9];
    float* out = (float*)d_out;

    cudaFuncSetAttribute(chebnet_mma_kernel,
                         cudaFuncAttributeMaxDynamicSharedMemorySize, SMEM_TOTAL);

    prep_weights<<<(4 * 128 * 128) / 256, 256>>>(W0, W1, W2, W3);
    chebnet_mma_kernel<<<NBLOCKS, THREADS, SMEM_TOTAL>>>(x, b0, b1, b2, b3, out);
}